// round 10
// baseline (speedup 1.0000x reference)
#include <cuda_runtime.h>
#include <cuda_pipeline.h>
#include <math.h>

#define N_TOK  16384
#define DIM    4096
#define NEXP   64
#define TOPK   8
#define NTHR   256               // 8 warps: 7 compute + all stage
#define KC     64
#define KSTEPS (KC / 16)         // 4
#define NCHUNK (DIM / KC)        // 64
#define NUNIT  (N_TOK / 16)      // 1024 m16 units
#define NCTA   148
#define PADF   72                // floats per slab row
#define SLAB_B (16 * PADF * 4)   // 4608 bytes per slab

typedef unsigned int u32;

// Packed W fp16 fragment quads: [kchunk][ks][n][t] -> {b0_hi, b1_hi, b0_lo*2048, b1_lo*2048}
__device__ __align__(16) uint4 g_Wq[NCHUNK * KSTEPS * NEXP * 4];   // 1 MB
__device__ float g_partial[NUNIT * NEXP];                           // per-unit expert sums
__device__ unsigned g_ticket = 0;

// ---- smem byte offsets ----
#define XS(b)  ((b) * (7 * SLAB_B))             // 2 x 32256
#define WQ(b)  (64512 + (b) * 16384)            // 2 x 1024 uint4
#define BIAS_S 97280
#define SMEM_BYTES 97536
// epilogue per-warp logits region (aliases XS(0) after loop): wid*4224, 16x66 floats

static __device__ __forceinline__ void split2(float x0, float x1, u32& h, u32& l) {
    asm("{\n\t"
        ".reg .b16 h0, h1;\n\t"
        ".reg .f32 u0, u1, r0, r1;\n\t"
        "cvt.rn.f16.f32 h0, %2;\n\t"
        "cvt.rn.f16.f32 h1, %3;\n\t"
        "mov.b32 %0, {h0, h1};\n\t"
        "cvt.f32.f16 u0, h0;\n\t"
        "cvt.f32.f16 u1, h1;\n\t"
        "sub.f32 r0, %2, u0;\n\t"
        "sub.f32 r1, %3, u1;\n\t"
        "mul.f32 r0, r0, 0f45000000;\n\t"
        "mul.f32 r1, r1, 0f45000000;\n\t"
        "cvt.rn.f16x2.f32 %1, r1, r0;\n\t"
        "}" : "=r"(h), "=r"(l) : "f"(x0), "f"(x1));
}
static __device__ __forceinline__ void mma_f16(float* c, u32 a0, u32 a1, u32 a2,
                                               u32 a3, u32 b0, u32 b1) {
    asm volatile(
        "mma.sync.aligned.m16n8k16.row.col.f32.f16.f16.f32 "
        "{%0,%1,%2,%3}, {%4,%5,%6,%7}, {%8,%9}, {%0,%1,%2,%3};"
        : "+f"(c[0]), "+f"(c[1]), "+f"(c[2]), "+f"(c[3])
        : "r"(a0), "r"(a1), "r"(a2), "r"(a3), "r"(b0), "r"(b1));
}
static __device__ __forceinline__ void mma_f16_z(float* d, u32 a0, u32 a1, u32 a2,
                                                 u32 a3, u32 b0, u32 b1) {
    asm volatile(
        "mma.sync.aligned.m16n8k16.row.col.f32.f16.f16.f32 "
        "{%0,%1,%2,%3}, {%4,%5,%6,%7}, {%8,%9}, {%10,%10,%10,%10};"
        : "=f"(d[0]), "=f"(d[1]), "=f"(d[2]), "=f"(d[3])
        : "r"(a0), "r"(a1), "r"(a2), "r"(a3), "r"(b0), "r"(b1), "f"(0.0f));
}

extern "C" __global__ void wconv_kernel(const float* __restrict__ W) {
    const int idx = blockIdx.x * blockDim.x + threadIdx.x;   // 65536 quads
    const int t  = idx & 3;
    const int n  = (idx >> 2) & 63;
    const int ks = (idx >> 8) & 3;
    const int c  = idx >> 10;
    const int k0 = c * KC + ks * 16;
    const float* wr = W + (size_t)n * DIM + k0;
    uint4 q;
    split2(wr[2 * t],     wr[2 * t + 1], q.x, q.z);
    split2(wr[2 * t + 8], wr[2 * t + 9], q.y, q.w);
    g_Wq[idx] = q;
}

extern "C" __global__ void __launch_bounds__(NTHR, 1)
moe_fused(const float* __restrict__ x, const float* __restrict__ bias,
          float* __restrict__ out) {
    extern __shared__ char sm[];
    __shared__ int s_last;
    __shared__ float s_part[4][NEXP];
    __shared__ float s_sq[NEXP];

    const int bid  = blockIdx.x;
    const int tid  = threadIdx.x;
    const int wid  = tid >> 5;
    const int lane = tid & 31;
    const int g    = lane >> 2;
    const int t    = lane & 3;

    const int u    = bid + NCTA * wid;              // unit for this warp
    const bool act = (wid < 7) && (u < NUNIT);
    // number of resident x slabs for this CTA (uniform across threads)
    const int nslab = (bid + NCTA * 6 < NUNIT) ? 7 : 6;

    if (tid < NEXP) reinterpret_cast<float*>(sm + BIAS_S)[tid] = bias[tid];

    auto issue_chunk = [&](int c) {
        const int b  = c & 1;
        const int kc = c * KC;
        const int row = tid >> 4, j = tid & 15;     // one float4 per thread per slab
        for (int s = 0; s < nslab; s++) {
            const int us = bid + NCTA * s;
            __pipeline_memcpy_async(sm + XS(b) + s * SLAB_B + row * (PADF * 4) + j * 16,
                                    x + (size_t)(us * 16 + row) * DIM + kc + 4 * j, 16);
        }
        const uint4* src = g_Wq + (size_t)c * (KSTEPS * NEXP * 4);
#pragma unroll
        for (int i = 0; i < 4; i++) {
            const int flat = tid + (i << 8);
            __pipeline_memcpy_async(sm + WQ(b) + flat * 16, src + flat, 16);
        }
    };

    float accM[8][4];
    float hh[8][4];
    float accx[8][4];
#pragma unroll
    for (int j = 0; j < 8; j++)
#pragma unroll
        for (int q = 0; q < 4; q++) { accM[j][q] = 0.f; accx[j][q] = 0.f; }

    issue_chunk(0);
    __pipeline_commit();

#pragma unroll 1
    for (int c = 0; c < NCHUNK; c++) {
        const int b = c & 1;
        if (c + 1 < NCHUNK) issue_chunk(c + 1);
        __pipeline_commit();
        __pipeline_wait_prior((c + 1 < NCHUNK) ? 1 : 0);
        __syncthreads();

        if (act) {
            const float* xs = reinterpret_cast<const float*>(sm + XS(b) + wid * SLAB_B);
            const uint4* wq = reinterpret_cast<const uint4*>(sm + WQ(b));
#pragma unroll
            for (int ks = 0; ks < KSTEPS; ks++) {
                const int k0 = ks * 16;
                const float2 v0 = *reinterpret_cast<const float2*>(xs + g * PADF + k0 + 2 * t);
                const float2 v1 = *reinterpret_cast<const float2*>(xs + (g + 8) * PADF + k0 + 2 * t);
                const float2 v2 = *reinterpret_cast<const float2*>(xs + g * PADF + k0 + 2 * t + 8);
                const float2 v3 = *reinterpret_cast<const float2*>(xs + (g + 8) * PADF + k0 + 2 * t + 8);
                u32 ah0, ah1, ah2, ah3, al0, al1, al2, al3;
                split2(v0.x, v0.y, ah0, al0);
                split2(v1.x, v1.y, ah1, al1);
                split2(v2.x, v2.y, ah2, al2);
                split2(v3.x, v3.y, ah3, al3);

                const uint4* wrow = wq + (ks * NEXP + g) * 4 + t;
#pragma unroll
                for (int j = 0; j < 8; j++) {
                    const uint4 q = wrow[j * 32];
                    if (ks == 0) mma_f16_z(hh[j], ah0, ah1, ah2, ah3, q.x, q.y);
                    else         mma_f16(hh[j], ah0, ah1, ah2, ah3, q.x, q.y);
                    mma_f16(accx[j], ah0, ah1, ah2, ah3, q.z, q.w);
                    mma_f16(accx[j], al0, al1, al2, al3, q.x, q.y);
                }
            }
#pragma unroll
            for (int j = 0; j < 8; j++)
#pragma unroll
                for (int q = 0; q < 4; q++) accM[j][q] += hh[j][q];
        }
        __syncthreads();
    }

    // ---- in-kernel epilogue (per active warp, private smem region) ----
    if (act) {
        float* lg = reinterpret_cast<float*>(sm + wid * 4224);   // 16 x 66
        const float s = 4.8828125e-4f;   // 1/2048
#pragma unroll
        for (int j = 0; j < 8; j++) {
            const int col = 8 * j + 2 * t;
            const float f0 = fmaf(accx[j][0], s, accM[j][0]);
            const float f1 = fmaf(accx[j][1], s, accM[j][1]);
            const float f2 = fmaf(accx[j][2], s, accM[j][2]);
            const float f3 = fmaf(accx[j][3], s, accM[j][3]);
            *reinterpret_cast<float2*>(lg + g * 66 + col)       = make_float2(f0, f1);
            *reinterpret_cast<float2*>(lg + (g + 8) * 66 + col) = make_float2(f2, f3);
        }
        __syncwarp();

        if (lane < 16) {
            const float* bs = reinterpret_cast<const float*>(sm + BIAS_S);
            float lv[NEXP];
            float mx = -INFINITY;
#pragma unroll
            for (int e = 0; e < NEXP; e++) {
                const float v = lg[lane * 66 + e] + bs[e];
                lv[e] = v;
                mx = fmaxf(mx, v);
            }
            float ssum = 0.0f;
#pragma unroll
            for (int e = 0; e < NEXP; e++) {
                lv[e] = expf(lv[e] - mx);
                ssum += lv[e];
            }
            const float inv = 1.0f / ssum;
#pragma unroll
            for (int e = 0; e < NEXP; e++) {
                lv[e] *= inv;
                lg[lane * 66 + e] = lv[e];
            }

            const int gt = u * 16 + lane;
            float prevV = INFINITY;
            int   prevE = -1;
            float* o_ids = out;
            float* o_p   = out + (size_t)N_TOK * 8;
#pragma unroll
            for (int r = 0; r < TOPK; r++) {
                float bv = -INFINITY;
                int   be = 0;
#pragma unroll
                for (int e = 0; e < NEXP; e++) {
                    const float v = lv[e];
                    const bool elig = (v < prevV) || (v == prevV && e > prevE);
                    if (elig && v > bv) { bv = v; be = e; }
                }
                o_ids[(size_t)gt * 8 + r] = (float)be;
                o_p[(size_t)gt * 8 + r]   = bv;
                prevV = bv; prevE = be;
            }
            out[(size_t)N_TOK * 16 + gt * 2 + 0] = 0.0f;
            out[(size_t)N_TOK * 16 + gt * 2 + 1] = 1.0f;
            out[(size_t)N_TOK * 18 + gt * 2 + 0] = 0.5f;
            out[(size_t)N_TOK * 18 + gt * 2 + 1] = 0.5f;
        }
        __syncwarp();

        // per-unit expert sums (lanes: e = lane, lane+32)
        float cs0 = 0.0f, cs1 = 0.0f;
#pragma unroll
        for (int tt = 0; tt < 16; tt++) {
            cs0 += lg[tt * 66 + lane];
            cs1 += lg[tt * 66 + lane + 32];
        }
        g_partial[u * NEXP + lane]      = cs0;
        g_partial[u * NEXP + lane + 32] = cs1;
    }

    // ---- last-CTA aux reduction (deterministic; ticket-gated) ----
    __syncthreads();
    __threadfence();
    if (tid == 0) {
        const unsigned v = atomicAdd(&g_ticket, 1u);
        s_last = (v == NCTA - 1) ? 1 : 0;
    }
    __syncthreads();
    if (s_last) {
        const int e  = tid & 63;
        const int gr = tid >> 6;     // 0..3, each sums 256 units
        float sum = 0.0f;
        for (int i = 0; i < NUNIT / 4; i++)
            sum += __ldcg(&g_partial[(size_t)(gr * (NUNIT / 4) + i) * NEXP + e]);
        s_part[gr][e] = sum;
        __syncthreads();
        if (tid < NEXP) {
            const float tot = s_part[0][tid] + s_part[1][tid] + s_part[2][tid] + s_part[3][tid];
            const float m = tot / (float)N_TOK;
            s_sq[tid] = m * m;
        }
        __syncthreads();
        if (tid == 0) {
            float tot = 0.0f;
            for (int i = 0; i < NEXP; i++) tot += s_sq[i];
            out[(size_t)N_TOK * 20] = 0.01f * (tot / (float)NEXP);
            g_ticket = 0;   // reset for next launch/replay
        }
    }
}

extern "C" void kernel_launch(void* const* d_in, const int* in_sizes, int n_in,
                              void* d_out, int out_size) {
    const float* x    = (const float*)d_in[0];
    const float* W    = (const float*)d_in[1];
    const float* bias = (const float*)d_in[2];
    float* out = (float*)d_out;

    cudaFuncSetAttribute(moe_fused, cudaFuncAttributeMaxDynamicSharedMemorySize,
                         SMEM_BYTES);
    wconv_kernel<<<256, 256>>>(W);
    moe_fused<<<NCTA, NTHR, SMEM_BYTES>>>(x, bias, out);
}

// round 11
// speedup vs baseline: 1.1397x; 1.1397x over previous
#include <cuda_runtime.h>
#include <cuda_pipeline.h>
#include <math.h>

#define N_TOK  16384
#define DIM    4096
#define NEXP   64
#define TOPK   8
#define TPB    128               // tokens per CTA
#define NTHR   512               // 16 warps: (m-tile, n-half)
#define KC     64
#define KSTEPS (KC / 16)         // 4
#define NCHUNK (DIM / KC)        // 64
#define NBLK   (N_TOK / TPB)     // 128
#define PAD    72                // x row stride in floats

typedef unsigned int u32;

// Packed W fp16 fragment quads: [kchunk][ks][n][t] -> {b0_hi, b1_hi, b0_lo*2048, b1_lo*2048}
__device__ __align__(16) uint4 g_Wq[NCHUNK * KSTEPS * NEXP * 4];   // 1 MB
__device__ float g_partial[NBLK * NEXP];

// ---- smem byte offsets ----
#define XS(b)  ((b) * 36864)                    // 128 x 72 floats
#define WQ(b)  (73728 + (b) * 16384)            // 1024 uint4
#define SMEM_BYTES 106496
#define PROBS  0                                 // phase-2 alias: float[128][66]
#define BIAS_S 33792                             // float[64]

static __device__ __forceinline__ void split2(float x0, float x1, u32& h, u32& l) {
    asm("{\n\t"
        ".reg .b16 h0, h1;\n\t"
        ".reg .f32 u0, u1, r0, r1;\n\t"
        "cvt.rn.f16.f32 h0, %2;\n\t"
        "cvt.rn.f16.f32 h1, %3;\n\t"
        "mov.b32 %0, {h0, h1};\n\t"
        "cvt.f32.f16 u0, h0;\n\t"
        "cvt.f32.f16 u1, h1;\n\t"
        "sub.f32 r0, %2, u0;\n\t"
        "sub.f32 r1, %3, u1;\n\t"
        "mul.f32 r0, r0, 0f45000000;\n\t"
        "mul.f32 r1, r1, 0f45000000;\n\t"
        "cvt.rn.f16x2.f32 %1, r1, r0;\n\t"
        "}" : "=r"(h), "=r"(l) : "f"(x0), "f"(x1));
}
static __device__ __forceinline__ void mma_f16(float* c, u32 a0, u32 a1, u32 a2,
                                               u32 a3, u32 b0, u32 b1) {
    asm volatile(
        "mma.sync.aligned.m16n8k16.row.col.f32.f16.f16.f32 "
        "{%0,%1,%2,%3}, {%4,%5,%6,%7}, {%8,%9}, {%0,%1,%2,%3};"
        : "+f"(c[0]), "+f"(c[1]), "+f"(c[2]), "+f"(c[3])
        : "r"(a0), "r"(a1), "r"(a2), "r"(a3), "r"(b0), "r"(b1));
}
static __device__ __forceinline__ void mma_f16_z(float* d, u32 a0, u32 a1, u32 a2,
                                                 u32 a3, u32 b0, u32 b1) {
    asm volatile(
        "mma.sync.aligned.m16n8k16.row.col.f32.f16.f16.f32 "
        "{%0,%1,%2,%3}, {%4,%5,%6,%7}, {%8,%9}, {%10,%10,%10,%10};"
        : "=f"(d[0]), "=f"(d[1]), "=f"(d[2]), "=f"(d[3])
        : "r"(a0), "r"(a1), "r"(a2), "r"(a3), "r"(b0), "r"(b1), "f"(0.0f));
}

extern "C" __global__ void wconv_kernel(const float* __restrict__ W) {
    const int idx = blockIdx.x * blockDim.x + threadIdx.x;   // 65536 quads
    const int t  = idx & 3;
    const int n  = (idx >> 2) & 63;
    const int ks = (idx >> 8) & 3;
    const int c  = idx >> 10;
    const int k0 = c * KC + ks * 16;
    const float* wr = W + (size_t)n * DIM + k0;
    uint4 q;
    split2(wr[2 * t],     wr[2 * t + 1], q.x, q.z);
    split2(wr[2 * t + 8], wr[2 * t + 9], q.y, q.w);
    g_Wq[idx] = q;
}

extern "C" __global__ void __launch_bounds__(NTHR, 1)
moe_main(const float* __restrict__ x, const float* __restrict__ bias,
         float* __restrict__ out) {
    extern __shared__ char sm[];
    const int tid  = threadIdx.x;
    const int wid  = tid >> 5;           // 0..15
    const int lane = tid & 31;
    const int g    = lane >> 2;          // 0..7
    const int t    = lane & 3;           // 0..3
    const int wm   = wid >> 1;           // m-tile 0..7
    const int wn   = wid & 1;            // n-half 0..1
    const int tok0 = blockIdx.x * TPB;
    const int warpM = wm * 16;

    // ---- cp.async stagers (512 threads) ----
    auto issue_chunk = [&](int c) {
        const int b  = c & 1;
        const int kc = c * KC;
        // x: 2048 float4 -> 4 per thread
#pragma unroll
        for (int i = 0; i < 4; i++) {
            const int flat = tid + (i << 9);
            const int row = flat >> 4;
            const int j   = flat & 15;
            __pipeline_memcpy_async(sm + XS(b) + row * (PAD * 4) + j * 16,
                                    x + (size_t)(tok0 + row) * DIM + kc + 4 * j, 16);
        }
        // W quads: 1024 uint4 -> 2 per thread
        const uint4* src = g_Wq + (size_t)c * (KSTEPS * NEXP * 4);
#pragma unroll
        for (int i = 0; i < 2; i++) {
            const int flat = tid + (i << 9);
            __pipeline_memcpy_async(sm + WQ(b) + flat * 16, src + flat, 16);
        }
    };

    // ---- accumulators: 4 n-tiles per warp ----
    float accM[4][4];
    float hh[4][4];
    float accx[4][4];
#pragma unroll
    for (int j = 0; j < 4; j++)
#pragma unroll
        for (int q = 0; q < 4; q++) { accM[j][q] = 0.f; accx[j][q] = 0.f; }

    issue_chunk(0);
    __pipeline_commit();

#pragma unroll 1
    for (int c = 0; c < NCHUNK; c++) {
        const int b = c & 1;
        if (c + 1 < NCHUNK) issue_chunk(c + 1);
        __pipeline_commit();
        __pipeline_wait_prior((c + 1 < NCHUNK) ? 1 : 0);
        __syncthreads();

        const float* xs = reinterpret_cast<const float*>(sm + XS(b));
        const uint4* wq = reinterpret_cast<const uint4*>(sm + WQ(b));

#pragma unroll
        for (int ks = 0; ks < KSTEPS; ks++) {
            const int k0 = ks * 16;
            const int r0 = warpM + g;
            const float2 v0 = *reinterpret_cast<const float2*>(xs + r0 * PAD + k0 + 2 * t);
            const float2 v1 = *reinterpret_cast<const float2*>(xs + (r0 + 8) * PAD + k0 + 2 * t);
            const float2 v2 = *reinterpret_cast<const float2*>(xs + r0 * PAD + k0 + 2 * t + 8);
            const float2 v3 = *reinterpret_cast<const float2*>(xs + (r0 + 8) * PAD + k0 + 2 * t + 8);
            u32 ah0, ah1, ah2, ah3, al0, al1, al2, al3;
            split2(v0.x, v0.y, ah0, al0);
            split2(v1.x, v1.y, ah1, al1);
            split2(v2.x, v2.y, ah2, al2);
            split2(v3.x, v3.y, ah3, al3);

            const uint4* wrow = wq + (ks * NEXP + g) * 4 + t;
#pragma unroll
            for (int j = 0; j < 4; j++) {
                const int jj = wn * 4 + j;
                const uint4 q = wrow[jj * 32];
                if (ks == 0) mma_f16_z(hh[j], ah0, ah1, ah2, ah3, q.x, q.y);
                else         mma_f16(hh[j], ah0, ah1, ah2, ah3, q.x, q.y);
                mma_f16(accx[j], ah0, ah1, ah2, ah3, q.z, q.w);
                mma_f16(accx[j], al0, al1, al2, al3, q.x, q.y);
            }
        }
#pragma unroll
        for (int j = 0; j < 4; j++)
#pragma unroll
            for (int q = 0; q < 4; q++) accM[j][q] += hh[j][q];
        __syncthreads();
    }

    // ---- epilogue: logits = accM + accx / 2048 ----
    float* ps = reinterpret_cast<float*>(sm + PROBS);   // [128][66]
    {
        const int r0 = warpM + g;
        const float s = 4.8828125e-4f;   // 1/2048
#pragma unroll
        for (int j = 0; j < 4; j++) {
            const int col = 8 * (wn * 4 + j) + 2 * t;
            const float f0 = fmaf(accx[j][0], s, accM[j][0]);
            const float f1 = fmaf(accx[j][1], s, accM[j][1]);
            const float f2 = fmaf(accx[j][2], s, accM[j][2]);
            const float f3 = fmaf(accx[j][3], s, accM[j][3]);
            *reinterpret_cast<float2*>(ps + r0 * 66 + col)       = make_float2(f0, f1);
            *reinterpret_cast<float2*>(ps + (r0 + 8) * 66 + col) = make_float2(f2, f3);
        }
    }
    if (tid < NEXP) reinterpret_cast<float*>(sm + BIAS_S)[tid] = bias[tid];
    __syncthreads();

    // ---- phase 2: softmax + top-8 (threads 0..127, thread == token) ----
    const int tok = tid;
    float lv[NEXP];
    if (tok < TPB) {
        const float* bs = reinterpret_cast<const float*>(sm + BIAS_S);
        float mx = -INFINITY;
#pragma unroll
        for (int e = 0; e < NEXP; e++) {
            const float v = ps[tok * 66 + e] + bs[e];
            lv[e] = v;
            mx = fmaxf(mx, v);
        }
        float ssum = 0.0f;
#pragma unroll
        for (int e = 0; e < NEXP; e++) {
            lv[e] = expf(lv[e] - mx);
            ssum += lv[e];
        }
        const float inv = 1.0f / ssum;
#pragma unroll
        for (int e = 0; e < NEXP; e++) lv[e] *= inv;
    }
    __syncthreads();
    if (tok < TPB) {
#pragma unroll
        for (int e = 0; e < NEXP; e++) ps[tok * 66 + e] = lv[e];
    }
    __syncthreads();

    if (tid < NEXP) {
        float cs = 0.0f;
        for (int tt = 0; tt < TPB; tt++) cs += ps[tt * 66 + tid];
        g_partial[blockIdx.x * NEXP + tid] = cs;
    }

    if (tok < TPB) {
        const int gt = tok0 + tok;
        float prevV = INFINITY;
        int   prevE = -1;
        float* o_ids = out;
        float* o_p   = out + (size_t)N_TOK * 8;
#pragma unroll
        for (int r = 0; r < TOPK; r++) {
            float bv = -INFINITY;
            int   be = 0;
#pragma unroll
            for (int e = 0; e < NEXP; e++) {
                const float v = lv[e];
                const bool elig = (v < prevV) || (v == prevV && e > prevE);
                if (elig && v > bv) { bv = v; be = e; }
            }
            o_ids[(size_t)gt * 8 + r] = (float)be;
            o_p[(size_t)gt * 8 + r]   = bv;
            prevV = bv; prevE = be;
        }
        out[(size_t)N_TOK * 16 + gt * 2 + 0] = 0.0f;
        out[(size_t)N_TOK * 16 + gt * 2 + 1] = 1.0f;
        out[(size_t)N_TOK * 18 + gt * 2 + 0] = 0.5f;
        out[(size_t)N_TOK * 18 + gt * 2 + 1] = 0.5f;
    }
}

// 512 threads: 8 tile-groups x 64 experts, then tree-reduce
__global__ void aux_kernel(float* __restrict__ out) {
    __shared__ float part[8][NEXP];
    __shared__ float sq[NEXP];
    const int e  = threadIdx.x & 63;
    const int gr = threadIdx.x >> 6;
    float s = 0.0f;
#pragma unroll
    for (int b = gr; b < NBLK; b += 8) s += g_partial[b * NEXP + e];
    part[gr][e] = s;
    __syncthreads();
    if (threadIdx.x < NEXP) {
        float tot = 0.0f;
#pragma unroll
        for (int i = 0; i < 8; i++) tot += part[i][threadIdx.x];
        const float m = tot / (float)N_TOK;
        sq[threadIdx.x] = m * m;
    }
    __syncthreads();
    if (threadIdx.x == 0) {
        float tot = 0.0f;
        for (int i = 0; i < NEXP; i++) tot += sq[i];
        out[(size_t)N_TOK * 20] = 0.01f * (tot / (float)NEXP);
    }
}

extern "C" void kernel_launch(void* const* d_in, const int* in_sizes, int n_in,
                              void* d_out, int out_size) {
    const float* x    = (const float*)d_in[0];
    const float* W    = (const float*)d_in[1];
    const float* bias = (const float*)d_in[2];
    float* out = (float*)d_out;

    cudaFuncSetAttribute(moe_main, cudaFuncAttributeMaxDynamicSharedMemorySize,
                         SMEM_BYTES);
    wconv_kernel<<<256, 256>>>(W);
    moe_main<<<NBLK, NTHR, SMEM_BYTES>>>(x, bias, out);
    aux_kernel<<<1, 512>>>(out);
}

// round 12
// speedup vs baseline: 1.2225x; 1.0726x over previous
#include <cuda_runtime.h>
#include <cuda_pipeline.h>
#include <math.h>

#define N_TOK  16384
#define DIM    4096
#define NEXP   64
#define TOPK   8
#define TPB    128               // tokens per CTA
#define NTHR   256               // 8 warps, warp = m16 tile
#define KC     64
#define KSTEPS (KC / 16)         // 4
#define NCHUNK (DIM / KC)        // 64
#define NBLK   (N_TOK / TPB)     // 128
#define PAD    72                // x row stride in floats

typedef unsigned int u32;

// Packed W fp16 fragment quads: [kchunk][ks][n][t] -> {b0_hi, b1_hi, b0_lo*2048, b1_lo*2048}
__device__ __align__(16) uint4 g_Wq[NCHUNK * KSTEPS * NEXP * 4];   // 1 MB
__device__ float g_partial[NBLK * NEXP];

// ---- smem byte offsets ----
#define XS(b)  ((b) * 36864)                    // 128 x 72 floats
#define WQ(b)  (73728 + (b) * 16384)            // 1024 uint4
#define SMEM_BYTES 106496
#define PROBS  0                                 // phase-2 alias: float[128][66]
#define BIAS_S 33792                             // float[64]

static __device__ __forceinline__ void split2(float x0, float x1, u32& h, u32& l) {
    asm("{\n\t"
        ".reg .b16 h0, h1;\n\t"
        ".reg .f32 u0, u1, r0, r1;\n\t"
        "cvt.rn.f16.f32 h0, %2;\n\t"
        "cvt.rn.f16.f32 h1, %3;\n\t"
        "mov.b32 %0, {h0, h1};\n\t"
        "cvt.f32.f16 u0, h0;\n\t"
        "cvt.f32.f16 u1, h1;\n\t"
        "sub.f32 r0, %2, u0;\n\t"
        "sub.f32 r1, %3, u1;\n\t"
        "mul.f32 r0, r0, 0f45000000;\n\t"
        "mul.f32 r1, r1, 0f45000000;\n\t"
        "cvt.rn.f16x2.f32 %1, r1, r0;\n\t"
        "}" : "=r"(h), "=r"(l) : "f"(x0), "f"(x1));
}
static __device__ __forceinline__ void mma_f16(float* c, u32 a0, u32 a1, u32 a2,
                                               u32 a3, u32 b0, u32 b1) {
    asm volatile(
        "mma.sync.aligned.m16n8k16.row.col.f32.f16.f16.f32 "
        "{%0,%1,%2,%3}, {%4,%5,%6,%7}, {%8,%9}, {%0,%1,%2,%3};"
        : "+f"(c[0]), "+f"(c[1]), "+f"(c[2]), "+f"(c[3])
        : "r"(a0), "r"(a1), "r"(a2), "r"(a3), "r"(b0), "r"(b1));
}
static __device__ __forceinline__ void mma_f16_z(float* d, u32 a0, u32 a1, u32 a2,
                                                 u32 a3, u32 b0, u32 b1) {
    asm volatile(
        "mma.sync.aligned.m16n8k16.row.col.f32.f16.f16.f32 "
        "{%0,%1,%2,%3}, {%4,%5,%6,%7}, {%8,%9}, {%10,%10,%10,%10};"
        : "=f"(d[0]), "=f"(d[1]), "=f"(d[2]), "=f"(d[3])
        : "r"(a0), "r"(a1), "r"(a2), "r"(a3), "r"(b0), "r"(b1), "f"(0.0f));
}

extern "C" __global__ void wconv_kernel(const float* __restrict__ W) {
    const int idx = blockIdx.x * blockDim.x + threadIdx.x;   // 65536 quads
    const int t  = idx & 3;
    const int n  = (idx >> 2) & 63;
    const int ks = (idx >> 8) & 3;
    const int c  = idx >> 10;
    const int k0 = c * KC + ks * 16;
    const float* wr = W + (size_t)n * DIM + k0;
    uint4 q;
    split2(wr[2 * t],     wr[2 * t + 1], q.x, q.z);
    split2(wr[2 * t + 8], wr[2 * t + 9], q.y, q.w);
    g_Wq[idx] = q;
}

extern "C" __global__ void __launch_bounds__(NTHR, 1)
moe_main(const float* __restrict__ x, const float* __restrict__ bias,
         float* __restrict__ out) {
    extern __shared__ char sm[];
    const int tid  = threadIdx.x;
    const int wid  = tid >> 5;
    const int lane = tid & 31;
    const int g    = lane >> 2;
    const int t    = lane & 3;
    const int tok0 = blockIdx.x * TPB;
    const int warpM = wid * 16;

    auto issue_chunk = [&](int c) {
        const int b  = c & 1;
        const int kc = c * KC;
#pragma unroll
        for (int i = 0; i < 8; i++) {
            const int flat = tid + (i << 8);
            const int row = flat >> 4;
            const int j   = flat & 15;
            __pipeline_memcpy_async(sm + XS(b) + row * (PAD * 4) + j * 16,
                                    x + (size_t)(tok0 + row) * DIM + kc + 4 * j, 16);
        }
        const uint4* src = g_Wq + (size_t)c * (KSTEPS * NEXP * 4);
#pragma unroll
        for (int i = 0; i < 4; i++) {
            const int flat = tid + (i << 8);
            __pipeline_memcpy_async(sm + WQ(b) + flat * 16, src + flat, 16);
        }
    };

    // ---- accumulators: all MMA chains depth-4 per chunk ----
    float accM[8][4];    // master fp32 (RN adds)
    float hh[8][4];      // per-chunk hi*hi (reset via mma_f16_z at ks==0)
    float axA[8][4];     // cross hi*lo(scaled), chained depth 4/chunk
    float axB[8][4];     // cross lo(scaled)*hi, chained depth 4/chunk
#pragma unroll
    for (int j = 0; j < 8; j++)
#pragma unroll
        for (int q = 0; q < 4; q++) {
            accM[j][q] = 0.f; axA[j][q] = 0.f; axB[j][q] = 0.f;
        }

    issue_chunk(0);
    __pipeline_commit();

#pragma unroll 1
    for (int c = 0; c < NCHUNK; c++) {
        const int b = c & 1;
        if (c + 1 < NCHUNK) issue_chunk(c + 1);
        __pipeline_commit();
        __pipeline_wait_prior((c + 1 < NCHUNK) ? 1 : 0);
        __syncthreads();

        const float* xs = reinterpret_cast<const float*>(sm + XS(b));
        const uint4* wq = reinterpret_cast<const uint4*>(sm + WQ(b));

#pragma unroll
        for (int ks = 0; ks < KSTEPS; ks++) {
            const int k0 = ks * 16;
            const int r0 = warpM + g;
            const float2 v0 = *reinterpret_cast<const float2*>(xs + r0 * PAD + k0 + 2 * t);
            const float2 v1 = *reinterpret_cast<const float2*>(xs + (r0 + 8) * PAD + k0 + 2 * t);
            const float2 v2 = *reinterpret_cast<const float2*>(xs + r0 * PAD + k0 + 2 * t + 8);
            const float2 v3 = *reinterpret_cast<const float2*>(xs + (r0 + 8) * PAD + k0 + 2 * t + 8);
            u32 ah0, ah1, ah2, ah3, al0, al1, al2, al3;
            split2(v0.x, v0.y, ah0, al0);
            split2(v1.x, v1.y, ah1, al1);
            split2(v2.x, v2.y, ah2, al2);
            split2(v3.x, v3.y, ah3, al3);

            const uint4* wrow = wq + (ks * NEXP + g) * 4 + t;
#pragma unroll
            for (int j = 0; j < 8; j++) {
                const uint4 q = wrow[j * 32];
                if (ks == 0) mma_f16_z(hh[j], ah0, ah1, ah2, ah3, q.x, q.y);
                else         mma_f16(hh[j], ah0, ah1, ah2, ah3, q.x, q.y);
                mma_f16(axA[j], ah0, ah1, ah2, ah3, q.z, q.w);   // hi * lo(scaled)
                mma_f16(axB[j], al0, al1, al2, al3, q.x, q.y);   // lo(scaled) * hi
            }
        }
#pragma unroll
        for (int j = 0; j < 8; j++)
#pragma unroll
            for (int q = 0; q < 4; q++) accM[j][q] += hh[j][q];
        __syncthreads();
    }

    // ---- epilogue: logits = accM + (axA + axB) / 2048 ----
    float* ps = reinterpret_cast<float*>(sm + PROBS);   // [128][66]
    {
        const int r0 = warpM + g;
        const float s = 4.8828125e-4f;   // 1/2048
#pragma unroll
        for (int j = 0; j < 8; j++) {
            const int col = 8 * j + 2 * t;
            const float f0 = fmaf(axA[j][0] + axB[j][0], s, accM[j][0]);
            const float f1 = fmaf(axA[j][1] + axB[j][1], s, accM[j][1]);
            const float f2 = fmaf(axA[j][2] + axB[j][2], s, accM[j][2]);
            const float f3 = fmaf(axA[j][3] + axB[j][3], s, accM[j][3]);
            *reinterpret_cast<float2*>(ps + r0 * 66 + col)       = make_float2(f0, f1);
            *reinterpret_cast<float2*>(ps + (r0 + 8) * 66 + col) = make_float2(f2, f3);
        }
    }
    if (tid < NEXP) reinterpret_cast<float*>(sm + BIAS_S)[tid] = bias[tid];
    __syncthreads();

    // ---- phase 2: softmax + top-8 (threads 0..127, thread == token) ----
    const int tok = tid;
    float lv[NEXP];
    if (tok < TPB) {
        const float* bs = reinterpret_cast<const float*>(sm + BIAS_S);
        float mx = -INFINITY;
#pragma unroll
        for (int e = 0; e < NEXP; e++) {
            const float v = ps[tok * 66 + e] + bs[e];
            lv[e] = v;
            mx = fmaxf(mx, v);
        }
        float ssum = 0.0f;
#pragma unroll
        for (int e = 0; e < NEXP; e++) {
            lv[e] = expf(lv[e] - mx);
            ssum += lv[e];
        }
        const float inv = 1.0f / ssum;
#pragma unroll
        for (int e = 0; e < NEXP; e++) lv[e] *= inv;
    }
    __syncthreads();
    if (tok < TPB) {
#pragma unroll
        for (int e = 0; e < NEXP; e++) ps[tok * 66 + e] = lv[e];
    }
    __syncthreads();

    if (tid < NEXP) {
        float cs = 0.0f;
        for (int tt = 0; tt < TPB; tt++) cs += ps[tt * 66 + tid];
        g_partial[blockIdx.x * NEXP + tid] = cs;
    }

    if (tok < TPB) {
        const int gt = tok0 + tok;
        float prevV = INFINITY;
        int   prevE = -1;
        float* o_ids = out;
        float* o_p   = out + (size_t)N_TOK * 8;
#pragma unroll
        for (int r = 0; r < TOPK; r++) {
            float bv = -INFINITY;
            int   be = 0;
#pragma unroll
            for (int e = 0; e < NEXP; e++) {
                const float v = lv[e];
                const bool elig = (v < prevV) || (v == prevV && e > prevE);
                if (elig && v > bv) { bv = v; be = e; }
            }
            o_ids[(size_t)gt * 8 + r] = (float)be;
            o_p[(size_t)gt * 8 + r]   = bv;
            prevV = bv; prevE = be;
        }
        out[(size_t)N_TOK * 16 + gt * 2 + 0] = 0.0f;
        out[(size_t)N_TOK * 16 + gt * 2 + 1] = 1.0f;
        out[(size_t)N_TOK * 18 + gt * 2 + 0] = 0.5f;
        out[(size_t)N_TOK * 18 + gt * 2 + 1] = 0.5f;
    }
}

// 512 threads: 8 tile-groups x 64 experts, then tree-reduce
__global__ void aux_kernel(float* __restrict__ out) {
    __shared__ float part[8][NEXP];
    __shared__ float sq[NEXP];
    const int e  = threadIdx.x & 63;
    const int gr = threadIdx.x >> 6;
    float s = 0.0f;
#pragma unroll
    for (int b = gr; b < NBLK; b += 8) s += g_partial[b * NEXP + e];
    part[gr][e] = s;
    __syncthreads();
    if (threadIdx.x < NEXP) {
        float tot = 0.0f;
#pragma unroll
        for (int i = 0; i < 8; i++) tot += part[i][threadIdx.x];
        const float m = tot / (float)N_TOK;
        sq[threadIdx.x] = m * m;
    }
    __syncthreads();
    if (threadIdx.x == 0) {
        float tot = 0.0f;
        for (int i = 0; i < NEXP; i++) tot += sq[i];
        out[(size_t)N_TOK * 20] = 0.01f * (tot / (float)NEXP);
    }
}

extern "C" void kernel_launch(void* const* d_in, const int* in_sizes, int n_in,
                              void* d_out, int out_size) {
    const float* x    = (const float*)d_in[0];
    const float* W    = (const float*)d_in[1];
    const float* bias = (const float*)d_in[2];
    float* out = (float*)d_out;

    cudaFuncSetAttribute(moe_main, cudaFuncAttributeMaxDynamicSharedMemorySize,
                         SMEM_BYTES);
    wconv_kernel<<<256, 256>>>(W);
    moe_main<<<NBLK, NTHR, SMEM_BYTES>>>(x, bias, out);
    aux_kernel<<<1, 512>>>(out);
}